// round 10
// baseline (speedup 1.0000x reference)
#include <cuda_runtime.h>
#include <stdint.h>

#define NBINS   29
#define BB      64
#define CC      4
#define QQ      32
#define DD      4096

#define THREADS 256
#define TPC     64            // threads per channel group
#define HALVES  2             // D-split per row
#define DH      (DD / HALVES) // 2048 elements per half
#define CHUNK   4             // iterations prefetched together
#define NCHUNK  2             // 8 float4 iterations per thread (2048/(64*4))

#define OUT_ELEMS (BB * CC * QQ * NBINS)
#define HIST_WORDS (NBINS * THREADS)   // 29*256 u32 words = 29.7 KB

__device__ __forceinline__ void proc_elem(float x, int m, uint8_t* col) {
    // bit-exact: ((x + 1.00001) / 2 * 28) trunc -> int.
    // (x+c)*0.5 is exact, so ((x+c)*0.5)*28 == (x+c)*14 with identical rounding.
    float t = __fmul_rn(__fadd_rn(x, 1.00001f), 14.0f);
    unsigned bin = (unsigned)__float2int_rz(t);
    bin = min(bin, 28u);                 // memory-safety clamp only
    if (m) col[bin << 10] += (uint8_t)1; // stride 1024 B per bin
}

__global__ void zero_out_kernel(float* __restrict__ out) {
    int i = blockIdx.x * blockDim.x + threadIdx.x;
    if (i < OUT_ELEMS) out[i] = 0.0f;
}

__global__ __launch_bounds__(THREADS)
void CountHistogram_kernel(const float* __restrict__ simmat,
                           const int* __restrict__ mask,
                           float* __restrict__ out) {
    // 4 u8 streams per thread (one per float4 lane).
    // byte = bin*1024 + 4*tid + s -> word = bin*256 + tid -> bank = tid%32:
    // conflict-free for any bin pattern, 4 independent RMW chains per thread.
    __shared__ uint32_t histw[HIST_WORDS];
    uint8_t* hist8 = (uint8_t*)histw;

    const int tid  = threadIdx.x;
    const int blk  = blockIdx.x;           // 0 .. B*Q*HALVES-1
    const int half = blk & (HALVES - 1);
    const int bq   = blk >> 1;             // 0 .. B*Q-1
    const int b    = bq / QQ;
    const int q    = bq % QQ;

    #pragma unroll
    for (int i = 0; i < NBINS; i++) histw[i * THREADS + tid] = 0u;
    __syncthreads();

    const int c      = tid >> 6;           // channel group 0..3
    const int lane64 = tid & 63;

    const float4* srow = (const float4*)(simmat +
                          ((((size_t)b * CC + c) * QQ + q) * (size_t)DD) +
                          (size_t)half * DH);
    const int4*   mrow = (const int4*)(mask +
                          (((size_t)b * QQ + q) * (size_t)DD) +
                          (size_t)half * DH);

    uint8_t* col = hist8 + 4 * tid;        // stream s uses col + s

    // Software pipeline: 8 LDG.128 per chunk, batched one chunk ahead.
    float4 sA[CHUNK]; int4 mA[CHUNK];
    #pragma unroll
    for (int j = 0; j < CHUNK; j++) {
        const int v = lane64 + j * TPC;
        sA[j] = srow[v];
        mA[j] = mrow[v];
    }

    #pragma unroll
    for (int chunk = 0; chunk < NCHUNK; chunk++) {
        float4 sB[CHUNK]; int4 mB[CHUNK];
        if (chunk < NCHUNK - 1) {
            #pragma unroll
            for (int j = 0; j < CHUNK; j++) {
                const int v = lane64 + ((chunk + 1) * CHUNK + j) * TPC;
                sB[j] = srow[v];
                mB[j] = mrow[v];
            }
        }
        #pragma unroll
        for (int j = 0; j < CHUNK; j++) {
            proc_elem(sA[j].x, mA[j].x, col + 0);
            proc_elem(sA[j].y, mA[j].y, col + 1);
            proc_elem(sA[j].z, mA[j].z, col + 2);
            proc_elem(sA[j].w, mA[j].w, col + 3);
        }
        #pragma unroll
        for (int j = 0; j < CHUNK; j++) { sA[j] = sB[j]; mA[j] = mB[j]; }
    }
    __syncthreads();

    // Partial (c, bin) = sum of 256 bytes = 64 u32 words via dp4a, then
    // accumulate into gmem (counts are ints <= 4096 -> fp32 add is exact,
    // so atomic order doesn't matter). Rotate j by bin: conflict-free.
    if (tid < CC * NBINS) {
        const int co  = tid / NBINS;
        const int bin = tid % NBINS;
        const uint32_t* base = histw + bin * THREADS + co * TPC;
        unsigned s = 0u;
        #pragma unroll 8
        for (int i = 0; i < TPC; i++) {
            const int j = (bin + i) & (TPC - 1);
            s = __dp4a(base[j], 0x01010101u, s);
        }
        atomicAdd(&out[((((size_t)b * CC + co) * QQ + q) * NBINS) + bin],
                  (float)s);
    }
}

extern "C" void kernel_launch(void* const* d_in, const int* in_sizes, int n_in,
                              void* d_out, int out_size) {
    const float* simmat = (const float*)d_in[0];
    const int*   mask   = (const int*)d_in[1];
    float*       out    = (float*)d_out;
    (void)in_sizes; (void)n_in; (void)out_size;

    zero_out_kernel<<<(OUT_ELEMS + 511) / 512, 512>>>(out);
    CountHistogram_kernel<<<BB * QQ * HALVES, THREADS>>>(simmat, mask, out);
}